// round 9
// baseline (speedup 1.0000x reference)
#include <cuda_runtime.h>
#include <math.h>

#define NN    4096
#define RR    4
#define FINN  128
#define HH    64
#define CC    16
#define LLAY  2
#define TT    512
#define ELL_S 128   // max nnz/row (mean ~21.5) incl. padding to multiple of 8
#define NH    (NN*HH)

// ---- static scratch (fp32) ----
__device__ float g_d    [RR*NN];                      // D^-1/2 per (relation,row)
__device__ int   g_cnt  [RR*NN];                      // true nnz
__device__ int   g_cntp [RR*NN];                      // nnz padded to multiple of 8
__device__ int   g_cols [RR*NN*ELL_S];                // ELL column indices (pad: self)
__device__ float g_dw   [RR*NN*ELL_S];                // d_j per slot (pad: 0)
__device__ __align__(16) float g_Y [RR*NN*HH];        // GEMM out (UNscaled)
__device__ __align__(16) float g_h [RR*NN*HH];        // GCN hidden, planes [r][j][h]
__device__ __align__(16) float g_tX[NN*HH*RR];        // interleaved [i][h][r] (head input)
// Ping-pong plane buffers (cross-block race otherwise — R6/R7 failure).
__device__ __align__(16) float g_X02[2][NN*2*HH];     // packed planes {0,2} per node
__device__ __align__(16) float g_X1 [2][NN*HH];       // plane 1
__device__ float g_What[LLAY*3*HH*HH];
__device__ float g_losses[TT];
__device__ float g_yscratch[TT*CC];

// ------------------------------------------------------------------
// K1: single dense pass over A -> ELL pattern (padded) + degrees.
// ------------------------------------------------------------------
__global__ void k_build(const float* __restrict__ A) {
    int warp = (blockIdx.x * blockDim.x + threadIdx.x) >> 5;
    int lane = threadIdx.x & 31;
    if (warp >= RR * NN) return;
    int i = warp & (NN - 1);
    const float4* row4 = (const float4*)(A + (size_t)warp * NN);
    int* crow = g_cols + (size_t)warp * ELL_S;
    unsigned bm = (1u << lane) - 1u;
    int cnt = 0;
    #pragma unroll 4
    for (int it = 0; it < NN / 128; it++) {
        float4 v = __ldcs(&row4[it * 32 + lane]);
        int jb = it * 128 + lane * 4;
        bool n0 = (v.x != 0.f) || (jb     == i);
        bool n1 = (v.y != 0.f) || (jb + 1 == i);
        bool n2 = (v.z != 0.f) || (jb + 2 == i);
        bool n3 = (v.w != 0.f) || (jb + 3 == i);
        unsigned m0 = __ballot_sync(0xffffffffu, n0);
        unsigned m1 = __ballot_sync(0xffffffffu, n1);
        unsigned m2 = __ballot_sync(0xffffffffu, n2);
        unsigned m3 = __ballot_sync(0xffffffffu, n3);
        int p = cnt + __popc(m0 & bm) + __popc(m1 & bm) + __popc(m2 & bm) + __popc(m3 & bm);
        if (n0) { if (p < ELL_S) crow[p] = jb;     p++; }
        if (n1) { if (p < ELL_S) crow[p] = jb + 1; p++; }
        if (n2) { if (p < ELL_S) crow[p] = jb + 2; p++; }
        if (n3) { if (p < ELL_S) crow[p] = jb + 3; p++; }
        cnt += __popc(m0) + __popc(m1) + __popc(m2) + __popc(m3);
    }
    if (cnt > ELL_S) cnt = ELL_S;
    int pad = (cnt + 7) & ~7;
    if (pad > ELL_S) pad = ELL_S;
    for (int s = cnt + lane; s < pad; s += 32) crow[s] = i;   // pad with self index
    if (lane == 0) {
        g_cnt[warp]  = cnt;
        g_cntp[warp] = pad;
        g_d[warp] = rsqrtf((float)cnt);   // rowsum == cnt, cnt>=1
    }
}

// K1b merged: blocks [0,2048): dw (0 for pad slots); [2048,2080): What;
// [2080,2592): xw1 (independent of build outputs since Y is unscaled).
__global__ void __launch_bounds__(256) k_prep_xw1(const float* __restrict__ W,
                                                  const float* __restrict__ X,
                                                  const float* __restrict__ W1) {
    int b = blockIdx.x;
    if (b < 2048) {
        int row = b * 8 + (threadIdx.x >> 5);
        int lane = threadIdx.x & 31;
        int rbase = row & ~(NN - 1);
        int cnt = g_cnt[row], cntp = g_cntp[row];
        const int* crow = g_cols + (size_t)row * ELL_S;
        float* dwr = g_dw + (size_t)row * ELL_S;
        for (int s = lane; s < cntp; s += 32)
            dwr[s] = (s < cnt) ? g_d[rbase + crow[s]] : 0.f;
    } else if (b < 2080) {
        int idx = (b - 2048) * 256 + threadIdx.x;   // < LLAY*HH*HH = 8192
        const float* p = W + (size_t)idx * RR;
        float w0 = p[0], w1 = p[1], w2 = p[2], w3 = p[3];
        int l = idx >> 12, q = idx & 4095;
        float* base = g_What + (size_t)l * 3 * HH * HH;
        base[q]           = w0 + w1 + w2 + w3;
        base[HH*HH + q]   = w0 - w2;
        base[2*HH*HH + q] = w0 - w1 + w2 - w3;
    } else {
        // xw1: Y[r,j,:] = X[j,:] @ W1[r]  (unscaled), 32 rows/block
        extern __shared__ float dsm[];
        float* sW = dsm;                 // FINN*HH = 32KB
        float* sX = dsm + FINN * HH;     // 32*FINN = 16KB
        int fb = b - 2080;               // 0..511
        int r = fb >> 7, bx = fb & 127;
        int i0 = bx * 32, tid = threadIdx.x;
        const float4* wg4 = (const float4*)(W1 + (size_t)r * FINN * HH);
        float4* sW4 = (float4*)sW;
        for (int q = tid; q < FINN * HH / 4; q += 256) sW4[q] = wg4[q];
        const float4* xg4 = (const float4*)(X + (size_t)i0 * FINN);
        float4* sX4 = (float4*)sX;
        for (int q = tid; q < 32 * FINN / 4; q += 256) sX4[q] = xg4[q];
        __syncthreads();
        int h = tid & 63, rg = tid >> 6;
        const float* sXb = sX + rg * 8 * FINN;
        float acc[8];
        #pragma unroll
        for (int rr = 0; rr < 8; rr++) acc[rr] = 0.f;
        for (int f = 0; f < FINN; f += 4) {
            float w0 = sW[f*64+h], w1 = sW[(f+1)*64+h], w2 = sW[(f+2)*64+h], w3 = sW[(f+3)*64+h];
            #pragma unroll
            for (int rr = 0; rr < 8; rr++) {
                float4 x = *(const float4*)&sXb[rr * FINN + f];
                acc[rr] += x.x*w0 + x.y*w1 + x.z*w2 + x.w*w3;
            }
        }
        #pragma unroll
        for (int rr = 0; rr < 8; rr++) {
            int gi = (r << 12) + i0 + rg * 8 + rr;
            g_Y[(size_t)gi * HH + h] = acc[rr];
        }
    }
}

// K4a: Y[r,j,:] = h[r,j,:] @ W2[r]  (unscaled).  32 rows/block, grid 512.
__global__ void __launch_bounds__(256) k_hw2(const float* __restrict__ W2) {
    __shared__ float sW[HH * HH];    // 16KB
    __shared__ float sX[32 * HH];    // 8KB
    int r = blockIdx.y, i0 = blockIdx.x * 32, tid = threadIdx.x;
    const float4* wg4 = (const float4*)(W2 + (size_t)r * HH * HH);
    float4* sW4 = (float4*)sW;
    for (int q = tid; q < HH * HH / 4; q += 256) sW4[q] = wg4[q];
    const float4* hg4 = (const float4*)(g_h + ((size_t)((r << 12) + i0)) * HH);
    float4* sX4 = (float4*)sX;
    for (int q = tid; q < 32 * HH / 4; q += 256) sX4[q] = hg4[q];
    __syncthreads();
    int h = tid & 63, rg = tid >> 6;
    const float* sXb = sX + rg * 8 * HH;
    float acc[8];
    #pragma unroll
    for (int rr = 0; rr < 8; rr++) acc[rr] = 0.f;
    for (int f = 0; f < HH; f += 4) {
        float w0 = sW[f*64+h], w1 = sW[(f+1)*64+h], w2 = sW[(f+2)*64+h], w3 = sW[(f+3)*64+h];
        #pragma unroll
        for (int rr = 0; rr < 8; rr++) {
            float4 x = *(const float4*)&sXb[rr * HH + f];
            acc[rr] += x.x*w0 + x.y*w1 + x.z*w2 + x.w*w3;
        }
    }
    #pragma unroll
    for (int rr = 0; rr < 8; rr++) {
        int gi = (r << 12) + i0 + rg * 8 + rr;
        g_Y[(size_t)gi * HH + h] = acc[rr];
    }
}

// K3: first GCN aggregation. Warp handles TWO rows interleaved (MLP x2),
// weighted by dw (pad slots weight 0 -> tail-free unroll-8 loop).
__global__ void __launch_bounds__(256) k_spmm_gcn(const float* __restrict__ bias) {
    int wid = threadIdx.x >> 5, lane = threadIdx.x & 31;
    int row0 = blockIdx.x * 16 + wid * 2;
    int row1 = row0 + 1;
    int r = row0 >> 12;
    int c0 = g_cntp[row0], c1 = g_cntp[row1];
    const int*   cr0 = g_cols + (size_t)row0 * ELL_S;
    const float* w0p = g_dw   + (size_t)row0 * ELL_S;
    const int*   cr1 = g_cols + (size_t)row1 * ELL_S;
    const float* w1p = g_dw   + (size_t)row1 * ELL_S;
    const float2* Y2 = (const float2*)g_Y + (((size_t)r) << 12) * 32;
    float a0x = 0.f, a0y = 0.f, a1x = 0.f, a1y = 0.f;
    int cm = c0 > c1 ? c0 : c1;
    for (int s = 0; s < cm; s += 8) {
        if (s < c0) {
            int j[8]; float w[8];
            #pragma unroll
            for (int u = 0; u < 8; u++) { j[u] = cr0[s+u]; w[u] = w0p[s+u]; }
            #pragma unroll
            for (int u = 0; u < 8; u++) {
                float2 f = Y2[(size_t)j[u] * 32 + lane];
                a0x += w[u] * f.x; a0y += w[u] * f.y;
            }
        }
        if (s < c1) {
            int j[8]; float w[8];
            #pragma unroll
            for (int u = 0; u < 8; u++) { j[u] = cr1[s+u]; w[u] = w1p[s+u]; }
            #pragma unroll
            for (int u = 0; u < 8; u++) {
                float2 f = Y2[(size_t)j[u] * 32 + lane];
                a1x += w[u] * f.x; a1y += w[u] * f.y;
            }
        }
    }
    float bx = bias[r * HH + 2 * lane], by = bias[r * HH + 2 * lane + 1];
    float d0 = g_d[row0], d1 = g_d[row1];
    float2 o0, o1;
    o0.x = fmaxf(d0 * a0x + bx, 0.f); o0.y = fmaxf(d0 * a0y + by, 0.f);
    o1.x = fmaxf(d1 * a1x + bx, 0.f); o1.y = fmaxf(d1 * a1y + by, 0.f);
    ((float2*)g_h)[(size_t)row0 * 32 + lane] = o0;
    ((float2*)g_h)[(size_t)row1 * 32 + lane] = o1;
}

// K4b: second GCN aggregation (warp per (node,relation), 2 nodes/block, dw-
// weighted, tail-free) + fused frequency-plane packing into plane buffer 0.
__global__ void __launch_bounds__(256) k_spmm_xhat(const float* __restrict__ bias) {
    __shared__ float2 sh[2][4][32];
    int tid = threadIdx.x;
    int wid = tid >> 5, lane = tid & 31;
    int nl = wid >> 2, r = wid & 3;
    int i = blockIdx.x * 2 + nl;
    int row = (r << 12) + i;
    int cntp = g_cntp[row];
    const int*   crow = g_cols + (size_t)row * ELL_S;
    const float* dwr  = g_dw   + (size_t)row * ELL_S;
    const float2* Y2 = (const float2*)g_Y + (((size_t)r) << 12) * 32;
    float ax = 0.f, ay = 0.f;
    for (int s = 0; s < cntp; s += 8) {
        int j[8]; float w[8];
        #pragma unroll
        for (int u = 0; u < 8; u++) { j[u] = crow[s+u]; w[u] = dwr[s+u]; }
        #pragma unroll
        for (int u = 0; u < 8; u++) {
            float2 f = Y2[(size_t)j[u] * 32 + lane];
            ax += w[u] * f.x; ay += w[u] * f.y;
        }
    }
    float di = g_d[row];
    float2 v;
    v.x = fmaxf(di * ax + bias[r * HH + 2 * lane], 0.f);
    v.y = fmaxf(di * ay + bias[r * HH + 2 * lane + 1], 0.f);
    sh[nl][r][lane] = v;
    __syncthreads();
    if (r == 0) {   // warps 0 and 4: plane epilogue for their node
        float2 x0 = sh[nl][0][lane], x1 = sh[nl][1][lane];
        float2 x2 = sh[nl][2][lane], x3 = sh[nl][3][lane];
        int f0 = 2 * lane, f1 = 2 * lane + 1;
        g_X02[0][(size_t)i * 128 + f0]      = x0.x + x1.x + x2.x + x3.x;  // plane0
        g_X02[0][(size_t)i * 128 + f1]      = x0.y + x1.y + x2.y + x3.y;
        g_X02[0][(size_t)i * 128 + 64 + f0] = x0.x - x1.x + x2.x - x3.x;  // plane2
        g_X02[0][(size_t)i * 128 + 64 + f1] = x0.y - x1.y + x2.y - x3.y;
        g_X1 [0][(size_t)i * 64 + f0]       = x0.x - x2.x;                // plane1
        g_X1 [0][(size_t)i * 64 + f1]       = x0.y - x2.y;
    }
}

// Fused MRGCO layer, 320 threads: gather phase interleaves 2 relations per
// thread (MLP x2, tail-free); then Ohat, Dhat (What via L1), final ifft+relu
// -> tX + next-layer planes. Ping-pong [src] -> [src^1].
__global__ void __launch_bounds__(320) k_mrgco(int layer, int write_next, int src) {
    __shared__ float part [4][128];
    __shared__ float part1[2][64];
    __shared__ float sO[3][HH];
    __shared__ float sD[3][HH];
    int i = blockIdx.x, tid = threadIdx.x;
    const float* X02s = g_X02[src];
    const float* X1s  = g_X1[src];
    if (tid < 256) {
        int ra = tid >> 7;          // 0 or 1; handles relations ra and ra+2
        int hh = tid & 127;
        int rowA = (ra << 12) + i, rowB = ((ra + 2) << 12) + i;
        int cA = g_cntp[rowA], cB = g_cntp[rowB];
        const int*   crA = g_cols + (size_t)rowA * ELL_S;
        const float* dwA = g_dw   + (size_t)rowA * ELL_S;
        const int*   crB = g_cols + (size_t)rowB * ELL_S;
        const float* dwB = g_dw   + (size_t)rowB * ELL_S;
        float sA = 0.f, sB = 0.f;
        int cm = cA > cB ? cA : cB;
        for (int s = 0; s < cm; s += 8) {
            if (s < cA) {
                int j[8]; float w[8];
                #pragma unroll
                for (int u = 0; u < 8; u++) { j[u] = crA[s+u]; w[u] = dwA[s+u]; }
                #pragma unroll
                for (int u = 0; u < 8; u++) sA += w[u] * X02s[(size_t)j[u] * 128 + hh];
            }
            if (s < cB) {
                int j[8]; float w[8];
                #pragma unroll
                for (int u = 0; u < 8; u++) { j[u] = crB[s+u]; w[u] = dwB[s+u]; }
                #pragma unroll
                for (int u = 0; u < 8; u++) sB += w[u] * X02s[(size_t)j[u] * 128 + hh];
            }
        }
        // plane0 (hh<64): coef=+1 all r.  plane2 (hh>=64): coef = (r&1)? -1:+1
        float cfA = (hh < 64) ? 1.f : ((ra & 1) ? -1.f : 1.f);
        float cfB = (hh < 64) ? 1.f : (((ra + 2) & 1) ? -1.f : 1.f);
        part[ra][hh]     = cfA * g_d[rowA] * sA;
        part[ra + 2][hh] = cfB * g_d[rowB] * sB;
    } else {
        int h = tid - 256;          // 0..63; plane 1, relations 0 and 2 interleaved
        int row0 = i, row2 = (2 << 12) + i;
        int c0 = g_cntp[row0], c2 = g_cntp[row2];
        const int*   cr0 = g_cols + (size_t)row0 * ELL_S;
        const float* dw0 = g_dw   + (size_t)row0 * ELL_S;
        const int*   cr2 = g_cols + (size_t)row2 * ELL_S;
        const float* dw2 = g_dw   + (size_t)row2 * ELL_S;
        float s0 = 0.f, s2 = 0.f;
        int cm = c0 > c2 ? c0 : c2;
        for (int s = 0; s < cm; s += 8) {
            if (s < c0) {
                int j[8]; float w[8];
                #pragma unroll
                for (int u = 0; u < 8; u++) { j[u] = cr0[s+u]; w[u] = dw0[s+u]; }
                #pragma unroll
                for (int u = 0; u < 8; u++) s0 += w[u] * X1s[(size_t)j[u] * 64 + h];
            }
            if (s < c2) {
                int j[8]; float w[8];
                #pragma unroll
                for (int u = 0; u < 8; u++) { j[u] = cr2[s+u]; w[u] = dw2[s+u]; }
                #pragma unroll
                for (int u = 0; u < 8; u++) s2 += w[u] * X1s[(size_t)j[u] * 64 + h];
            }
        }
        part1[0][h] =  g_d[row0] * s0;   // Mc[1][0] = +1
        part1[1][h] = -g_d[row2] * s2;   // Mc[1][2] = -1
    }
    __syncthreads();
    if (tid < HH) {
        float C0 = part[0][tid] + part[1][tid] + part[2][tid] + part[3][tid];
        float C2 = part[0][64+tid] + part[1][64+tid] + part[2][64+tid] + part[3][64+tid];
        float C1 = part1[0][tid] + part1[1][tid];
        float O0 = 0.25f * (C0 + 2.f*C1 + C2);
        float O1 = 0.25f * (C0 - C2);
        float O2 = 0.25f * (C0 - 2.f*C1 + C2);
        float O3 = O1;
        sO[0][tid] = O0 + O1 + O2 + O3;     // Ohat planes
        sO[1][tid] = O0 - O2;
        sO[2][tid] = O0 - O1 + O2 - O3;
    }
    __syncthreads();
    if (tid < 192) {
        int k = tid >> 6, l = tid & 63;
        const float* wk = g_What + (size_t)layer * 3 * HH * HH + (size_t)k * HH * HH;
        float acc = 0.f;
        #pragma unroll 8
        for (int j = 0; j < HH; j++)
            acc += sO[k][j] * __ldg(&wk[j * HH + l]);
        sD[k][l] = acc;
    }
    __syncthreads();
    if (tid < HH) {
        float D0 = sD[0][tid], D1 = sD[1][tid], D2 = sD[2][tid];
        float v0 = 0.25f * (D0 + 2.f*D1 + D2);
        float v1 = 0.25f * (D0 - D2);
        float v2 = 0.25f * (D0 - 2.f*D1 + D2);
        float v3 = v1;
        v0 = fmaxf(v0, 0.f);  v1 = fmaxf(v1, 0.f);
        v2 = fmaxf(v2, 0.f);  v3 = fmaxf(v3, 0.f);
        float4 tv; tv.x = v0; tv.y = v1; tv.z = v2; tv.w = v3;
        *(float4*)&g_tX[((size_t)i * HH + tid) * RR] = tv;
        if (write_next) {
            int dst = src ^ 1;
            g_X02[dst][(size_t)i * 128 + tid]      = v0 + v1 + v2 + v3;
            g_X02[dst][(size_t)i * 128 + 64 + tid] = v0 - v1 + v2 - v3;
            g_X1 [dst][(size_t)i * 64 + tid]       = v0 - v2;
        }
    }
}

// Head: 4 targets per block (grid 128), lin1_w cached in smem.
__global__ void k_head(const int* __restrict__ target_x, const int* __restrict__ target,
                       const float* __restrict__ l1w, const float* __restrict__ l1b,
                       const float* __restrict__ l2w, const float* __restrict__ l2b,
                       float* __restrict__ y_out) {
    extern __shared__ float dsm[];
    float* sw1 = dsm;                // 256*64 = 64KB
    float* sf  = sw1 + 256 * HH;     // 256
    float* sp  = sf + 256;           // 4*64
    float* szz = sp + 256;           // 64
    float* sy  = szz + 64;           // 16
    int tid = threadIdx.x;
    {
        const float4* w4 = (const float4*)l1w;
        float4* s4 = (float4*)sw1;
        for (int q = tid; q < 256 * HH / 4; q += 256) s4[q] = w4[q];
    }
    int h = tid & 63, part = tid >> 6;
    for (int tt = 0; tt < 4; tt++) {
        int t = blockIdx.x * 4 + tt;
        __syncthreads();
        int n = target_x[t];
        sf[tid] = g_tX[(size_t)n * 256 + tid];
        __syncthreads();
        float acc = 0.f;
        #pragma unroll 8
        for (int q = part * 64; q < part * 64 + 64; q++)
            acc += sf[q] * sw1[q * 64 + h];
        sp[part * 64 + h] = acc;
        __syncthreads();
        if (tid < HH) {
            float z = sp[tid] + sp[64 + tid] + sp[128 + tid] + sp[192 + tid] + l1b[tid];
            szz[tid] = fmaxf(z, 0.f);
        }
        __syncthreads();
        if (tid < CC) {
            float yv = l2b[tid];
            #pragma unroll 8
            for (int hh = 0; hh < HH; hh++) yv += szz[hh] * l2w[hh * CC + tid];
            sy[tid] = yv;
            y_out[t * CC + tid] = yv;
        }
        __syncthreads();
        if (tid == 0) {
            float mx = sy[0];
            for (int c = 1; c < CC; c++) mx = fmaxf(mx, sy[c]);
            float se = 0.f;
            for (int c = 0; c < CC; c++) se += expf(sy[c] - mx);
            g_losses[t] = mx + logf(se) - sy[target[t]];
        }
    }
}

__global__ void k_loss_reduce(float* __restrict__ loss_ptr) {
    __shared__ float s[256];
    int tid = threadIdx.x;
    s[tid] = g_losses[tid] + g_losses[tid + 256];
    __syncthreads();
    for (int o = 128; o > 0; o >>= 1) {
        if (tid < o) s[tid] += s[tid + o];
        __syncthreads();
    }
    if (tid == 0) *loss_ptr = s[0] / (float)TT;
}

extern "C" void kernel_launch(void* const* d_in, const int* in_sizes, int n_in,
                              void* d_out, int out_size) {
    const float* A        = (const float*)d_in[0];
    const float* X        = (const float*)d_in[1];
    const int*   target_x = (const int*)  d_in[2];
    const int*   target   = (const int*)  d_in[3];
    const float* gw1      = (const float*)d_in[4];
    const float* gb1      = (const float*)d_in[5];
    const float* gw2      = (const float*)d_in[6];
    const float* gb2      = (const float*)d_in[7];
    const float* mw       = (const float*)d_in[8];
    const float* l1w      = (const float*)d_in[9];
    const float* l1b      = (const float*)d_in[10];
    const float* l2w      = (const float*)d_in[11];
    const float* l2b      = (const float*)d_in[12];

    float* outf = (float*)d_out;
    float* loss_ptr = nullptr;
    float* y_dst;
    if (out_size >= TT * CC + 1)  { loss_ptr = outf; y_dst = outf + 1; }
    else if (out_size >= TT * CC) { y_dst = outf; }
    else {
        loss_ptr = outf;
        void* p = nullptr; cudaGetSymbolAddress(&p, g_yscratch);
        y_dst = (float*)p;
    }

    const int XW1_SMEM  = (FINN * HH + 32 * FINN) * 4;              // 48 KB
    const int HEAD_SMEM = (256 * HH + 256 + 256 + 64 + 16) * 4;     // ~66 KB
    cudaFuncSetAttribute(k_prep_xw1, cudaFuncAttributeMaxDynamicSharedMemorySize, XW1_SMEM);
    cudaFuncSetAttribute(k_head,     cudaFuncAttributeMaxDynamicSharedMemorySize, HEAD_SMEM);

    // 1) sparsity pattern + degrees (single DRAM pass over A)
    k_build<<<RR * NN / 8, 256>>>(A);
    // 2) merged: dw fill + What transform + X@W1 (concurrent block families)
    k_prep_xw1<<<2048 + 32 + 512, 256, XW1_SMEM>>>(mw, X, gw1);
    // 3) GCN aggregations + dense H@W2
    k_spmm_gcn<<<RR * NN / 16, 256>>>(gb1);
    k_hw2<<<dim3(NN / 32, RR), 256>>>(gw2);
    k_spmm_xhat<<<NN / 2, 256>>>(gb2);   // fused plane packing into buffer 0
    // 4) MRGCO layers (ping-pong plane buffers)
    for (int l = 0; l < LLAY; l++)
        k_mrgco<<<NN, 320>>>(l, l + 1 < LLAY, l & 1);
    // 5) head + deterministic loss reduction
    k_head<<<TT / 4, 256, HEAD_SMEM>>>(target_x, target, l1w, l1b, l2w, l2b, y_dst);
    if (loss_ptr) k_loss_reduce<<<1, 256>>>(loss_ptr);
}

// round 11
// speedup vs baseline: 1.0787x; 1.0787x over previous
#include <cuda_runtime.h>
#include <math.h>

#define NN    4096
#define RR    4
#define FINN  128
#define HH    64
#define CC    16
#define LLAY  2
#define TT    512
#define ELL_S 128   // max nnz/row (mean ~21.5) incl. padding to multiple of 8
#define NH    (NN*HH)

// ---- static scratch (fp32) ----
// RACE INVARIANT: gather kernels must never write the buffer they gather from.
// g_Y  : written by k_xw1, gathered by k_gcn2.
// g_Y2 : written by k_gcn2, gathered by k_spmm_xhat.
// plane buffers: ping-pong across k_mrgco layers.
__device__ float g_d    [RR*NN];                      // D^-1/2 per (relation,row)
__device__ int   g_cnt  [RR*NN];                      // true nnz
__device__ int   g_cntp [RR*NN];                      // nnz padded to multiple of 8
__device__ int   g_cols [RR*NN*ELL_S];                // ELL column indices (pad: self)
__device__ float g_dw   [RR*NN*ELL_S];                // d_j per slot (pad: 0)
__device__ __align__(16) float g_Y [RR*NN*HH];        // X@W1 (UNscaled)
__device__ __align__(16) float g_Y2[RR*NN*HH];        // relu(agg)@W2 (UNscaled)
__device__ __align__(16) float g_tX[NN*HH*RR];        // interleaved [i][h][r] (head input)
__device__ __align__(16) float g_X02[2][NN*2*HH];     // packed planes {0,2} per node
__device__ __align__(16) float g_X1 [2][NN*HH];       // plane 1
__device__ float g_What[LLAY*3*HH*HH];
__device__ float g_losses[TT];
__device__ float g_yscratch[TT*CC];

// ------------------------------------------------------------------
// K1: single dense pass over A -> ELL pattern (padded to mult of 8) + degrees.
// ------------------------------------------------------------------
__global__ void k_build(const float* __restrict__ A) {
    int warp = (blockIdx.x * blockDim.x + threadIdx.x) >> 5;
    int lane = threadIdx.x & 31;
    if (warp >= RR * NN) return;
    int i = warp & (NN - 1);
    const float4* row4 = (const float4*)(A + (size_t)warp * NN);
    int* crow = g_cols + (size_t)warp * ELL_S;
    unsigned bm = (1u << lane) - 1u;
    int cnt = 0;
    #pragma unroll 4
    for (int it = 0; it < NN / 128; it++) {
        float4 v = __ldcs(&row4[it * 32 + lane]);
        int jb = it * 128 + lane * 4;
        bool n0 = (v.x != 0.f) || (jb     == i);
        bool n1 = (v.y != 0.f) || (jb + 1 == i);
        bool n2 = (v.z != 0.f) || (jb + 2 == i);
        bool n3 = (v.w != 0.f) || (jb + 3 == i);
        unsigned m0 = __ballot_sync(0xffffffffu, n0);
        unsigned m1 = __ballot_sync(0xffffffffu, n1);
        unsigned m2 = __ballot_sync(0xffffffffu, n2);
        unsigned m3 = __ballot_sync(0xffffffffu, n3);
        int p = cnt + __popc(m0 & bm) + __popc(m1 & bm) + __popc(m2 & bm) + __popc(m3 & bm);
        if (n0) { if (p < ELL_S) crow[p] = jb;     p++; }
        if (n1) { if (p < ELL_S) crow[p] = jb + 1; p++; }
        if (n2) { if (p < ELL_S) crow[p] = jb + 2; p++; }
        if (n3) { if (p < ELL_S) crow[p] = jb + 3; p++; }
        cnt += __popc(m0) + __popc(m1) + __popc(m2) + __popc(m3);
    }
    if (cnt > ELL_S) cnt = ELL_S;
    int pad = (cnt + 7) & ~7;
    if (pad > ELL_S) pad = ELL_S;
    for (int s = cnt + lane; s < pad; s += 32) crow[s] = i;   // pad with self index
    if (lane == 0) {
        g_cnt[warp]  = cnt;
        g_cntp[warp] = pad;
        g_d[warp] = rsqrtf((float)cnt);   // rowsum == cnt, cnt>=1
    }
}

// K1b: NO dynamic smem. blocks [0,2048): dw (0 on pads); [2048,2080): What.
__global__ void __launch_bounds__(256) k_prep(const float* __restrict__ W) {
    int b = blockIdx.x;
    if (b < 2048) {
        int row = b * 8 + (threadIdx.x >> 5);
        int lane = threadIdx.x & 31;
        int rbase = row & ~(NN - 1);
        int cnt = g_cnt[row], cntp = g_cntp[row];
        const int* crow = g_cols + (size_t)row * ELL_S;
        float* dwr = g_dw + (size_t)row * ELL_S;
        for (int s = lane; s < cntp; s += 32)
            dwr[s] = (s < cnt) ? g_d[rbase + crow[s]] : 0.f;
    } else {
        int idx = (b - 2048) * 256 + threadIdx.x;   // < LLAY*HH*HH = 8192
        const float* p = W + (size_t)idx * RR;
        float w0 = p[0], w1 = p[1], w2 = p[2], w3 = p[3];
        int l = idx >> 12, q = idx & 4095;
        float* base = g_What + (size_t)l * 3 * HH * HH;
        base[q]           = w0 + w1 + w2 + w3;
        base[HH*HH + q]   = w0 - w2;
        base[2*HH*HH + q] = w0 - w1 + w2 - w3;
    }
}

// K2: Y[r,j,:] = X[j,:] @ W1[r]  (UNscaled).  32 rows/block, grid (128,4).
__global__ void __launch_bounds__(256) k_xw1(const float* __restrict__ X,
                                             const float* __restrict__ W1) {
    extern __shared__ float dsm[];
    float* sW = dsm;                 // FINN*HH = 32KB
    float* sX = dsm + FINN * HH;     // 32*FINN = 16KB
    int r = blockIdx.y, i0 = blockIdx.x * 32, tid = threadIdx.x;
    const float4* wg4 = (const float4*)(W1 + (size_t)r * FINN * HH);
    float4* sW4 = (float4*)sW;
    for (int q = tid; q < FINN * HH / 4; q += 256) sW4[q] = wg4[q];
    const float4* xg4 = (const float4*)(X + (size_t)i0 * FINN);
    float4* sX4 = (float4*)sX;
    for (int q = tid; q < 32 * FINN / 4; q += 256) sX4[q] = xg4[q];
    __syncthreads();
    int h = tid & 63, rg = tid >> 6;
    const float* sXb = sX + rg * 8 * FINN;
    float acc[8];
    #pragma unroll
    for (int rr = 0; rr < 8; rr++) acc[rr] = 0.f;
    for (int f = 0; f < FINN; f += 4) {
        float w0 = sW[f*64+h], w1 = sW[(f+1)*64+h], w2 = sW[(f+2)*64+h], w3 = sW[(f+3)*64+h];
        #pragma unroll
        for (int rr = 0; rr < 8; rr++) {
            float4 x = *(const float4*)&sXb[rr * FINN + f];
            acc[rr] += x.x*w0 + x.y*w1 + x.z*w2 + x.w*w3;
        }
    }
    #pragma unroll
    for (int rr = 0; rr < 8; rr++) {
        int gi = (r << 12) + i0 + rg * 8 + rr;
        g_Y[(size_t)gi * HH + h] = acc[rr];
    }
}

// K3 fused: first GCN aggregation (warp per row, dw-weighted, tail-free)
// + relu + @W2 GEMM in smem.  READS g_Y, WRITES g_Y2 (separate buffer:
// writing g_Y here races with other blocks' gathers — the R10 failure).
__global__ void __launch_bounds__(256) k_gcn2(const float* __restrict__ bias,
                                              const float* __restrict__ W2) {
    __shared__ float sW[HH * HH];    // 16KB: W2[r]
    __shared__ float sH[8][HH];      // 2KB: relu'd hidden rows
    int r = blockIdx.y, i0 = blockIdx.x * 8, tid = threadIdx.x;
    int wid = tid >> 5, lane = tid & 31;
    {   // load W2[r]
        const float4* wg4 = (const float4*)(W2 + (size_t)r * HH * HH);
        float4* sW4 = (float4*)sW;
        for (int q = tid; q < HH * HH / 4; q += 256) sW4[q] = wg4[q];
    }
    // gather phase: warp wid handles node i0+wid
    int row = (r << 12) + i0 + wid;
    int cntp = g_cntp[row];
    const int*   crow = g_cols + (size_t)row * ELL_S;
    const float* dwr  = g_dw   + (size_t)row * ELL_S;
    const float2* Y2 = (const float2*)g_Y + (((size_t)r) << 12) * 32;
    float ax = 0.f, ay = 0.f;
    for (int s = 0; s < cntp; s += 8) {
        int j[8]; float w[8];
        #pragma unroll
        for (int u = 0; u < 8; u++) { j[u] = crow[s+u]; w[u] = dwr[s+u]; }
        #pragma unroll
        for (int u = 0; u < 8; u++) {
            float2 f = Y2[(size_t)j[u] * 32 + lane];
            ax += w[u] * f.x; ay += w[u] * f.y;
        }
    }
    float di = g_d[row];
    sH[wid][2*lane]     = fmaxf(di * ax + bias[r * HH + 2*lane], 0.f);
    sH[wid][2*lane + 1] = fmaxf(di * ay + bias[r * HH + 2*lane + 1], 0.f);
    __syncthreads();
    // GEMM phase: thread computes rows rg and rg+4, column h
    int h = tid & 63, rg = tid >> 6;
    float a0 = 0.f, a1 = 0.f;
    #pragma unroll 8
    for (int j = 0; j < HH; j++) {
        float w = sW[j * 64 + h];
        a0 += sH[rg][j] * w;
        a1 += sH[rg + 4][j] * w;
    }
    int gb = (r << 12) + i0;
    g_Y2[(size_t)(gb + rg)     * HH + h] = a0;
    g_Y2[(size_t)(gb + rg + 4) * HH + h] = a1;
}

// K4: second GCN aggregation over g_Y2 (warp per (node,relation), 2 nodes/
// block, dw-weighted, tail-free) + fused frequency-plane packing into buffer 0.
__global__ void __launch_bounds__(256) k_spmm_xhat(const float* __restrict__ bias) {
    __shared__ float2 sh[2][4][32];
    int tid = threadIdx.x;
    int wid = tid >> 5, lane = tid & 31;
    int nl = wid >> 2, r = wid & 3;
    int i = blockIdx.x * 2 + nl;
    int row = (r << 12) + i;
    int cntp = g_cntp[row];
    const int*   crow = g_cols + (size_t)row * ELL_S;
    const float* dwr  = g_dw   + (size_t)row * ELL_S;
    const float2* Y2 = (const float2*)g_Y2 + (((size_t)r) << 12) * 32;
    float ax = 0.f, ay = 0.f;
    for (int s = 0; s < cntp; s += 8) {
        int j[8]; float w[8];
        #pragma unroll
        for (int u = 0; u < 8; u++) { j[u] = crow[s+u]; w[u] = dwr[s+u]; }
        #pragma unroll
        for (int u = 0; u < 8; u++) {
            float2 f = Y2[(size_t)j[u] * 32 + lane];
            ax += w[u] * f.x; ay += w[u] * f.y;
        }
    }
    float di = g_d[row];
    float2 v;
    v.x = fmaxf(di * ax + bias[r * HH + 2 * lane], 0.f);
    v.y = fmaxf(di * ay + bias[r * HH + 2 * lane + 1], 0.f);
    sh[nl][r][lane] = v;
    __syncthreads();
    if (r == 0) {   // warps 0 and 4: plane epilogue for their node
        float2 x0 = sh[nl][0][lane], x1 = sh[nl][1][lane];
        float2 x2 = sh[nl][2][lane], x3 = sh[nl][3][lane];
        int f0 = 2 * lane, f1 = 2 * lane + 1;
        g_X02[0][(size_t)i * 128 + f0]      = x0.x + x1.x + x2.x + x3.x;  // plane0
        g_X02[0][(size_t)i * 128 + f1]      = x0.y + x1.y + x2.y + x3.y;
        g_X02[0][(size_t)i * 128 + 64 + f0] = x0.x - x1.x + x2.x - x3.x;  // plane2
        g_X02[0][(size_t)i * 128 + 64 + f1] = x0.y - x1.y + x2.y - x3.y;
        g_X1 [0][(size_t)i * 64 + f0]       = x0.x - x2.x;                // plane1
        g_X1 [0][(size_t)i * 64 + f1]       = x0.y - x2.y;
    }
}

// Fused MRGCO layer (640 threads, tail-free loops): Chat gather, Ohat,
// Dhat (What via L1), final ifft+relu -> tX + next-layer planes.
// Ping-pong [src] -> [src^1].
__global__ void __launch_bounds__(640) k_mrgco(int layer, int write_next, int src) {
    __shared__ float part [4][128];
    __shared__ float part1[2][64];
    __shared__ float sO[3][HH];
    __shared__ float sD[3][HH];
    int i = blockIdx.x, tid = threadIdx.x;
    const float* X02s = g_X02[src];
    const float* X1s  = g_X1[src];
    if (tid < 512) {
        int r = tid >> 7, hh = tid & 127;
        int row = (r << 12) + i;
        int cntp = g_cntp[row];
        const int*   crow = g_cols + (size_t)row * ELL_S;
        const float* dwr  = g_dw   + (size_t)row * ELL_S;
        float s = 0.f;
        for (int ss = 0; ss < cntp; ss += 8) {
            int j[8]; float w[8];
            #pragma unroll
            for (int u = 0; u < 8; u++) { j[u] = crow[ss+u]; w[u] = dwr[ss+u]; }
            #pragma unroll
            for (int u = 0; u < 8; u++) s += w[u] * X02s[(size_t)j[u] * 128 + hh];
        }
        float coef = (hh < 64) ? 1.f : ((r & 1) ? -1.f : 1.f);   // Mc[0][r] / Mc[2][r]
        part[r][hh] = coef * g_d[row] * s;
    } else {
        int t2 = tid - 512;
        int rr = t2 >> 6, h = t2 & 63;
        int r = rr * 2;                                          // relations 0, 2
        int row = (r << 12) + i;
        int cntp = g_cntp[row];
        const int*   crow = g_cols + (size_t)row * ELL_S;
        const float* dwr  = g_dw   + (size_t)row * ELL_S;
        float s = 0.f;
        for (int ss = 0; ss < cntp; ss += 8) {
            int j[8]; float w[8];
            #pragma unroll
            for (int u = 0; u < 8; u++) { j[u] = crow[ss+u]; w[u] = dwr[ss+u]; }
            #pragma unroll
            for (int u = 0; u < 8; u++) s += w[u] * X1s[(size_t)j[u] * 64 + h];
        }
        part1[rr][h] = (rr ? -1.f : 1.f) * g_d[row] * s;         // Mc[1][0]=+1, Mc[1][2]=-1
    }
    __syncthreads();
    if (tid < HH) {
        float C0 = part[0][tid] + part[1][tid] + part[2][tid] + part[3][tid];
        float C2 = part[0][64+tid] + part[1][64+tid] + part[2][64+tid] + part[3][64+tid];
        float C1 = part1[0][tid] + part1[1][tid];
        float O0 = 0.25f * (C0 + 2.f*C1 + C2);
        float O1 = 0.25f * (C0 - C2);
        float O2 = 0.25f * (C0 - 2.f*C1 + C2);
        float O3 = O1;
        sO[0][tid] = O0 + O1 + O2 + O3;     // Ohat planes
        sO[1][tid] = O0 - O2;
        sO[2][tid] = O0 - O1 + O2 - O3;
    }
    __syncthreads();
    if (tid < 192) {
        int k = tid >> 6, l = tid & 63;
        const float* wk = g_What + (size_t)layer * 3 * HH * HH + (size_t)k * HH * HH;
        float acc = 0.f;
        #pragma unroll 8
        for (int j = 0; j < HH; j++)
            acc += sO[k][j] * __ldg(&wk[j * HH + l]);
        sD[k][l] = acc;
    }
    __syncthreads();
    if (tid < HH) {
        float D0 = sD[0][tid], D1 = sD[1][tid], D2 = sD[2][tid];
        float v0 = 0.25f * (D0 + 2.f*D1 + D2);
        float v1 = 0.25f * (D0 - D2);
        float v2 = 0.25f * (D0 - 2.f*D1 + D2);
        float v3 = v1;
        v0 = fmaxf(v0, 0.f);  v1 = fmaxf(v1, 0.f);
        v2 = fmaxf(v2, 0.f);  v3 = fmaxf(v3, 0.f);
        float4 tv; tv.x = v0; tv.y = v1; tv.z = v2; tv.w = v3;
        *(float4*)&g_tX[((size_t)i * HH + tid) * RR] = tv;
        if (write_next) {
            int dst = src ^ 1;
            g_X02[dst][(size_t)i * 128 + tid]      = v0 + v1 + v2 + v3;
            g_X02[dst][(size_t)i * 128 + 64 + tid] = v0 - v1 + v2 - v3;
            g_X1 [dst][(size_t)i * 64 + tid]       = v0 - v2;
        }
    }
}

// Head: 4 targets per block (grid 128), lin1_w cached in smem.
__global__ void k_head(const int* __restrict__ target_x, const int* __restrict__ target,
                       const float* __restrict__ l1w, const float* __restrict__ l1b,
                       const float* __restrict__ l2w, const float* __restrict__ l2b,
                       float* __restrict__ y_out) {
    extern __shared__ float dsm[];
    float* sw1 = dsm;                // 256*64 = 64KB
    float* sf  = sw1 + 256 * HH;     // 256
    float* sp  = sf + 256;           // 4*64
    float* szz = sp + 256;           // 64
    float* sy  = szz + 64;           // 16
    int tid = threadIdx.x;
    {
        const float4* w4 = (const float4*)l1w;
        float4* s4 = (float4*)sw1;
        for (int q = tid; q < 256 * HH / 4; q += 256) s4[q] = w4[q];
    }
    int h = tid & 63, part = tid >> 6;
    for (int tt = 0; tt < 4; tt++) {
        int t = blockIdx.x * 4 + tt;
        __syncthreads();
        int n = target_x[t];
        sf[tid] = g_tX[(size_t)n * 256 + tid];
        __syncthreads();
        float acc = 0.f;
        #pragma unroll 8
        for (int q = part * 64; q < part * 64 + 64; q++)
            acc += sf[q] * sw1[q * 64 + h];
        sp[part * 64 + h] = acc;
        __syncthreads();
        if (tid < HH) {
            float z = sp[tid] + sp[64 + tid] + sp[128 + tid] + sp[192 + tid] + l1b[tid];
            szz[tid] = fmaxf(z, 0.f);
        }
        __syncthreads();
        if (tid < CC) {
            float yv = l2b[tid];
            #pragma unroll 8
            for (int hh = 0; hh < HH; hh++) yv += szz[hh] * l2w[hh * CC + tid];
            sy[tid] = yv;
            y_out[t * CC + tid] = yv;
        }
        __syncthreads();
        if (tid == 0) {
            float mx = sy[0];
            for (int c = 1; c < CC; c++) mx = fmaxf(mx, sy[c]);
            float se = 0.f;
            for (int c = 0; c < CC; c++) se += expf(sy[c] - mx);
            g_losses[t] = mx + logf(se) - sy[target[t]];
        }
    }
}

__global__ void k_loss_reduce(float* __restrict__ loss_ptr) {
    __shared__ float s[256];
    int tid = threadIdx.x;
    s[tid] = g_losses[tid] + g_losses[tid + 256];
    __syncthreads();
    for (int o = 128; o > 0; o >>= 1) {
        if (tid < o) s[tid] += s[tid + o];
        __syncthreads();
    }
    if (tid == 0) *loss_ptr = s[0] / (float)TT;
}

extern "C" void kernel_launch(void* const* d_in, const int* in_sizes, int n_in,
                              void* d_out, int out_size) {
    const float* A        = (const float*)d_in[0];
    const float* X        = (const float*)d_in[1];
    const int*   target_x = (const int*)  d_in[2];
    const int*   target   = (const int*)  d_in[3];
    const float* gw1      = (const float*)d_in[4];
    const float* gb1      = (const float*)d_in[5];
    const float* gw2      = (const float*)d_in[6];
    const float* gb2      = (const float*)d_in[7];
    const float* mw       = (const float*)d_in[8];
    const float* l1w      = (const float*)d_in[9];
    const float* l1b      = (const float*)d_in[10];
    const float* l2w      = (const float*)d_in[11];
    const float* l2b      = (const float*)d_in[12];

    float* outf = (float*)d_out;
    float* loss_ptr = nullptr;
    float* y_dst;
    if (out_size >= TT * CC + 1)  { loss_ptr = outf; y_dst = outf + 1; }
    else if (out_size >= TT * CC) { y_dst = outf; }
    else {
        loss_ptr = outf;
        void* p = nullptr; cudaGetSymbolAddress(&p, g_yscratch);
        y_dst = (float*)p;
    }

    const int XW1_SMEM  = (FINN * HH + 32 * FINN) * 4;              // 48 KB
    const int HEAD_SMEM = (256 * HH + 256 + 256 + 64 + 16) * 4;     // ~66 KB
    cudaFuncSetAttribute(k_xw1,  cudaFuncAttributeMaxDynamicSharedMemorySize, XW1_SMEM);
    cudaFuncSetAttribute(k_head, cudaFuncAttributeMaxDynamicSharedMemorySize, HEAD_SMEM);

    // 1) sparsity pattern + degrees (single DRAM pass over A)
    k_build<<<RR * NN / 8, 256>>>(A);
    // 2) dw fill + What transform (no dynamic smem)
    k_prep<<<2048 + 32, 256>>>(mw);
    // 3) X @ W1 (unscaled) -> g_Y
    k_xw1<<<dim3(NN / 32, RR), 256, XW1_SMEM>>>(X, gw1);
    // 4) fused: aggregate(g_Y)+relu+(@W2) -> g_Y2
    k_gcn2<<<dim3(NN / 8, RR), 256>>>(gb1, gw2);
    // 5) second aggregation (g_Y2) + plane packing into buffer 0
    k_spmm_xhat<<<NN / 2, 256>>>(gb2);
    // 6) MRGCO layers (ping-pong plane buffers)
    for (int l = 0; l < LLAY; l++)
        k_mrgco<<<NN, 640>>>(l, l + 1 < LLAY, l & 1);
    // 7) head + deterministic loss reduction
    k_head<<<TT / 4, 256, HEAD_SMEM>>>(target_x, target, l1w, l1b, l2w, l2b, y_dst);
    if (loss_ptr) k_loss_reduce<<<1, 256>>>(loss_ptr);
}

// round 12
// speedup vs baseline: 1.3278x; 1.2310x over previous
#include <cuda_runtime.h>
#include <cuda_fp16.h>
#include <math.h>

#define NN    4096
#define RR    4
#define FINN  128
#define HH    64
#define CC    16
#define LLAY  2
#define TT    512
#define ELL_S 128   // max nnz/row (mean ~21.5, sigma ~4.5 -> huge margin)
#define NH    (NN*HH)

// ---- static scratch ----
// RACE INVARIANT: gather kernels must never write the buffer they gather from.
// g_Y  : written by k_xw1, gathered by k_gcn2.
// g_Y2 : written by k_gcn2, gathered by k_spmm_xhat.
// plane buffers (fp16): ping-pong across k_mrgco layers.
__device__ float g_d    [RR*NN];                      // D^-1/2 per (relation,row)
__device__ int   g_cnt  [RR*NN];                      // nnz per row
__device__ int   g_cols [RR*NN*ELL_S];                // ELL column indices
__device__ float g_dw   [RR*NN*ELL_S];                // d_j per slot (MRGCO only)
__device__ __align__(16) float g_Y [RR*NN*HH];        // X@W1, pre-scaled by d_j
__device__ __align__(16) float g_Y2[RR*NN*HH];        // relu(agg)@W2, pre-scaled by d_j
__device__ __align__(16) float g_tX[NN*HH*RR];        // interleaved [i][h][r] (head input)
// fp16 plane buffers: slot f of node i holds (plane0[f], plane2[f]); X1h slot q
// holds (plane1[2q], plane1[2q+1]). fp32 accumulation everywhere.
__device__ __align__(16) __half2 g_X02h[2][NN*HH];    // 1 MB each
__device__ __align__(16) __half2 g_X1h [2][NN*32];    // 0.5 MB each
__device__ float g_What[LLAY*3*HH*HH];
__device__ float g_losses[TT];
__device__ float g_yscratch[TT*CC];

// ------------------------------------------------------------------
// K1: single dense pass over A -> ELL pattern + degrees. Warp per row.
// (NO padding — R9/R11 showed +15% gather work costs more than tails.)
// ------------------------------------------------------------------
__global__ void k_build(const float* __restrict__ A) {
    int warp = (blockIdx.x * blockDim.x + threadIdx.x) >> 5;
    int lane = threadIdx.x & 31;
    if (warp >= RR * NN) return;
    int i = warp & (NN - 1);
    const float4* row4 = (const float4*)(A + (size_t)warp * NN);
    int* crow = g_cols + (size_t)warp * ELL_S;
    unsigned bm = (1u << lane) - 1u;
    int cnt = 0;
    #pragma unroll 4
    for (int it = 0; it < NN / 128; it++) {
        float4 v = __ldcs(&row4[it * 32 + lane]);
        int jb = it * 128 + lane * 4;
        bool n0 = (v.x != 0.f) || (jb     == i);
        bool n1 = (v.y != 0.f) || (jb + 1 == i);
        bool n2 = (v.z != 0.f) || (jb + 2 == i);
        bool n3 = (v.w != 0.f) || (jb + 3 == i);
        unsigned m0 = __ballot_sync(0xffffffffu, n0);
        unsigned m1 = __ballot_sync(0xffffffffu, n1);
        unsigned m2 = __ballot_sync(0xffffffffu, n2);
        unsigned m3 = __ballot_sync(0xffffffffu, n3);
        int p = cnt + __popc(m0 & bm) + __popc(m1 & bm) + __popc(m2 & bm) + __popc(m3 & bm);
        if (n0) { if (p < ELL_S) crow[p] = jb;     p++; }
        if (n1) { if (p < ELL_S) crow[p] = jb + 1; p++; }
        if (n2) { if (p < ELL_S) crow[p] = jb + 2; p++; }
        if (n3) { if (p < ELL_S) crow[p] = jb + 3; p++; }
        cnt += __popc(m0) + __popc(m1) + __popc(m2) + __popc(m3);
    }
    if (cnt > ELL_S) cnt = ELL_S;
    if (lane == 0) {
        g_cnt[warp] = cnt;
        g_d[warp] = rsqrtf((float)cnt);   // rowsum == cnt (entries exactly 1.0), cnt>=1
    }
}

// K1b: NO dynamic smem. blocks [0,2048): dw (MRGCO); [2048,2080): What.
__global__ void __launch_bounds__(256) k_prep(const float* __restrict__ W) {
    int b = blockIdx.x;
    if (b < 2048) {
        int row = b * 8 + (threadIdx.x >> 5);
        int lane = threadIdx.x & 31;
        int rbase = row & ~(NN - 1);
        int cnt = g_cnt[row];
        const int* crow = g_cols + (size_t)row * ELL_S;
        float* dwr = g_dw + (size_t)row * ELL_S;
        for (int s = lane; s < cnt; s += 32) dwr[s] = g_d[rbase + crow[s]];
    } else {
        int idx = (b - 2048) * 256 + threadIdx.x;   // < LLAY*HH*HH = 8192
        const float* p = W + (size_t)idx * RR;
        float w0 = p[0], w1 = p[1], w2 = p[2], w3 = p[3];
        int l = idx >> 12, q = idx & 4095;
        float* base = g_What + (size_t)l * 3 * HH * HH;
        base[q]           = w0 + w1 + w2 + w3;
        base[HH*HH + q]   = w0 - w2;
        base[2*HH*HH + q] = w0 - w1 + w2 - w3;
    }
}

// K2: Y[r,j,:] = d_rj * (X[j,:] @ W1[r]).  32 rows/block, grid (128,4).
__global__ void __launch_bounds__(256) k_xw1(const float* __restrict__ X,
                                             const float* __restrict__ W1) {
    extern __shared__ float dsm[];
    float* sW = dsm;                 // FINN*HH = 32KB
    float* sX = dsm + FINN * HH;     // 32*FINN = 16KB
    int r = blockIdx.y, i0 = blockIdx.x * 32, tid = threadIdx.x;
    const float4* wg4 = (const float4*)(W1 + (size_t)r * FINN * HH);
    float4* sW4 = (float4*)sW;
    for (int q = tid; q < FINN * HH / 4; q += 256) sW4[q] = wg4[q];
    const float4* xg4 = (const float4*)(X + (size_t)i0 * FINN);
    float4* sX4 = (float4*)sX;
    for (int q = tid; q < 32 * FINN / 4; q += 256) sX4[q] = xg4[q];
    __syncthreads();
    int h = tid & 63, rg = tid >> 6;
    const float* sXb = sX + rg * 8 * FINN;
    float acc[8];
    #pragma unroll
    for (int rr = 0; rr < 8; rr++) acc[rr] = 0.f;
    for (int f = 0; f < FINN; f += 4) {
        float w0 = sW[f*64+h], w1 = sW[(f+1)*64+h], w2 = sW[(f+2)*64+h], w3 = sW[(f+3)*64+h];
        #pragma unroll
        for (int rr = 0; rr < 8; rr++) {
            float4 x = *(const float4*)&sXb[rr * FINN + f];
            acc[rr] += x.x*w0 + x.y*w1 + x.z*w2 + x.w*w3;
        }
    }
    #pragma unroll
    for (int rr = 0; rr < 8; rr++) {
        int gi = (r << 12) + i0 + rg * 8 + rr;
        g_Y[(size_t)gi * HH + h] = g_d[gi] * acc[rr];
    }
}

// K3 fused: first GCN aggregation (warp per node, unweighted gathers of
// pre-scaled g_Y, unroll-8 + tail) + relu + @W2, output pre-scaled by d_row.
// READS g_Y, WRITES g_Y2 (separate buffer — race invariant).
__global__ void __launch_bounds__(256) k_gcn2(const float* __restrict__ bias,
                                              const float* __restrict__ W2) {
    __shared__ float sW[HH * HH];    // 16KB: W2[r]
    __shared__ float sH[8][HH];      // relu'd hidden rows
    int r = blockIdx.y, i0 = blockIdx.x * 8, tid = threadIdx.x;
    int wid = tid >> 5, lane = tid & 31;
    {
        const float4* wg4 = (const float4*)(W2 + (size_t)r * HH * HH);
        float4* sW4 = (float4*)sW;
        for (int q = tid; q < HH * HH / 4; q += 256) sW4[q] = wg4[q];
    }
    int row = (r << 12) + i0 + wid;
    int cnt = g_cnt[row];
    const int* crow = g_cols + (size_t)row * ELL_S;
    const float2* Y2 = (const float2*)g_Y + (((size_t)r) << 12) * 32;
    float ax = 0.f, ay = 0.f;
    int s = 0;
    for (; s + 8 <= cnt; s += 8) {
        int j[8];
        #pragma unroll
        for (int u = 0; u < 8; u++) j[u] = crow[s + u];
        #pragma unroll
        for (int u = 0; u < 8; u++) {
            float2 f = Y2[(size_t)j[u] * 32 + lane];
            ax += f.x; ay += f.y;
        }
    }
    for (; s < cnt; s++) {
        float2 f = Y2[(size_t)crow[s] * 32 + lane];
        ax += f.x; ay += f.y;
    }
    float di = g_d[row];
    sH[wid][2*lane]     = fmaxf(di * ax + bias[r * HH + 2*lane], 0.f);
    sH[wid][2*lane + 1] = fmaxf(di * ay + bias[r * HH + 2*lane + 1], 0.f);
    __syncthreads();
    int h = tid & 63, rg = tid >> 6;
    float a0 = 0.f, a1 = 0.f;
    #pragma unroll 8
    for (int j = 0; j < HH; j++) {
        float w = sW[j * 64 + h];
        a0 += sH[rg][j] * w;
        a1 += sH[rg + 4][j] * w;
    }
    int gb = (r << 12) + i0;
    g_Y2[(size_t)(gb + rg)     * HH + h] = g_d[gb + rg]     * a0;  // pre-scale
    g_Y2[(size_t)(gb + rg + 4) * HH + h] = g_d[gb + rg + 4] * a1;
}

// K4: second GCN aggregation over pre-scaled g_Y2 (warp per (node,relation),
// 2 nodes/block, unroll-8 + tail) + fused fp16 plane packing into buffer 0.
__global__ void __launch_bounds__(256) k_spmm_xhat(const float* __restrict__ bias) {
    __shared__ float2 sh[2][4][32];
    int tid = threadIdx.x;
    int wid = tid >> 5, lane = tid & 31;
    int nl = wid >> 2, r = wid & 3;
    int i = blockIdx.x * 2 + nl;
    int row = (r << 12) + i;
    int cnt = g_cnt[row];
    const int* crow = g_cols + (size_t)row * ELL_S;
    const float2* Y2 = (const float2*)g_Y2 + (((size_t)r) << 12) * 32;
    float ax = 0.f, ay = 0.f;
    int s = 0;
    for (; s + 8 <= cnt; s += 8) {
        int j[8];
        #pragma unroll
        for (int u = 0; u < 8; u++) j[u] = crow[s + u];
        #pragma unroll
        for (int u = 0; u < 8; u++) {
            float2 f = Y2[(size_t)j[u] * 32 + lane];
            ax += f.x; ay += f.y;
        }
    }
    for (; s < cnt; s++) {
        float2 f = Y2[(size_t)crow[s] * 32 + lane];
        ax += f.x; ay += f.y;
    }
    float di = g_d[row];
    float2 v;
    v.x = fmaxf(di * ax + bias[r * HH + 2 * lane], 0.f);
    v.y = fmaxf(di * ay + bias[r * HH + 2 * lane + 1], 0.f);
    sh[nl][r][lane] = v;
    __syncthreads();
    if (r == 0) {   // warps 0 and 4: fp16 plane epilogue for their node
        float2 x0 = sh[nl][0][lane], x1 = sh[nl][1][lane];
        float2 x2 = sh[nl][2][lane], x3 = sh[nl][3][lane];
        int f0 = 2 * lane, f1 = 2 * lane + 1;
        float p0x = x0.x + x1.x + x2.x + x3.x, p0y = x0.y + x1.y + x2.y + x3.y;
        float p2x = x0.x - x1.x + x2.x - x3.x, p2y = x0.y - x1.y + x2.y - x3.y;
        float p1x = x0.x - x2.x,               p1y = x0.y - x2.y;
        g_X02h[0][(size_t)i * HH + f0] = __floats2half2_rn(p0x, p2x);
        g_X02h[0][(size_t)i * HH + f1] = __floats2half2_rn(p0y, p2y);
        g_X1h [0][(size_t)i * 32 + lane] = __floats2half2_rn(p1x, p1y);
    }
}

// Fused MRGCO layer, 320 threads, fp16 plane gathers (fp32 accumulation):
//  tid<256: (r = tid>>6, f = tid&63) gathers half2 (p0,p2) per neighbor.
//  tid in [256,320): (rr = t>>5 -> rel 0/2, q = t&31) gathers plane1 half2.
// Then Ohat, Dhat (What via L1), final ifft+relu -> tX + next-layer fp16
// planes. Ping-pong [src] -> [src^1] (race invariant).
__global__ void __launch_bounds__(320) k_mrgco(int layer, int write_next, int src) {
    __shared__ float part0[4][HH];
    __shared__ float part2[4][HH];
    __shared__ float part1[2][HH];
    __shared__ float sO[3][HH];
    __shared__ float sD[3][HH];
    int i = blockIdx.x, tid = threadIdx.x;
    const __half2* X02s = g_X02h[src];
    const __half2* X1s  = g_X1h[src];
    if (tid < 256) {
        int r = tid >> 6, f = tid & 63;
        int row = (r << 12) + i;
        int cnt = g_cnt[row];
        const int*   crow = g_cols + (size_t)row * ELL_S;
        const float* dwr  = g_dw   + (size_t)row * ELL_S;
        float a0 = 0.f, a2 = 0.f;
        int ss = 0;
        for (; ss + 8 <= cnt; ss += 8) {
            int j[8]; float w[8];
            #pragma unroll
            for (int u = 0; u < 8; u++) { j[u] = crow[ss+u]; w[u] = dwr[ss+u]; }
            #pragma unroll
            for (int u = 0; u < 8; u++) {
                float2 x = __half22float2(X02s[(size_t)j[u] * HH + f]);
                a0 += w[u] * x.x; a2 += w[u] * x.y;
            }
        }
        for (; ss < cnt; ss++) {
            float2 x = __half22float2(X02s[(size_t)crow[ss] * HH + f]);
            a0 += dwr[ss] * x.x; a2 += dwr[ss] * x.y;
        }
        float di = g_d[row];
        float sgn = (r & 1) ? -1.f : 1.f;            // Mc[2][r]
        part0[r][f] = di * a0;                       // Mc[0][r] = +1
        part2[r][f] = sgn * di * a2;
    } else {
        int t2 = tid - 256;                          // 0..63
        int rr = t2 >> 5, q = t2 & 31;
        int r = rr * 2;                              // relations 0, 2
        int row = (r << 12) + i;
        int cnt = g_cnt[row];
        const int*   crow = g_cols + (size_t)row * ELL_S;
        const float* dwr  = g_dw   + (size_t)row * ELL_S;
        float ax = 0.f, ay = 0.f;
        int ss = 0;
        for (; ss + 8 <= cnt; ss += 8) {
            int j[8]; float w[8];
            #pragma unroll
            for (int u = 0; u < 8; u++) { j[u] = crow[ss+u]; w[u] = dwr[ss+u]; }
            #pragma unroll
            for (int u = 0; u < 8; u++) {
                float2 x = __half22float2(X1s[(size_t)j[u] * 32 + q]);
                ax += w[u] * x.x; ay += w[u] * x.y;
            }
        }
        for (; ss < cnt; ss++) {
            float2 x = __half22float2(X1s[(size_t)crow[ss] * 32 + q]);
            ax += dwr[ss] * x.x; ay += dwr[ss] * x.y;
        }
        float c = (rr ? -1.f : 1.f) * g_d[row];      // Mc[1][0]=+1, Mc[1][2]=-1
        part1[rr][2*q]     = c * ax;
        part1[rr][2*q + 1] = c * ay;
    }
    __syncthreads();
    if (tid < HH) {
        float C0 = part0[0][tid] + part0[1][tid] + part0[2][tid] + part0[3][tid];
        float C2 = part2[0][tid] + part2[1][tid] + part2[2][tid] + part2[3][tid];
        float C1 = part1[0][tid] + part1[1][tid];
        float O0 = 0.25f * (C0 + 2.f*C1 + C2);
        float O1 = 0.25f * (C0 - C2);
        float O2 = 0.25f * (C0 - 2.f*C1 + C2);
        float O3 = O1;
        sO[0][tid] = O0 + O1 + O2 + O3;     // Ohat planes
        sO[1][tid] = O0 - O2;
        sO[2][tid] = O0 - O1 + O2 - O3;
    }
    __syncthreads();
    if (tid < 192) {
        int k = tid >> 6, l = tid & 63;
        const float* wk = g_What + (size_t)layer * 3 * HH * HH + (size_t)k * HH * HH;
        float acc = 0.f;
        #pragma unroll 8
        for (int j = 0; j < HH; j++)
            acc += sO[k][j] * __ldg(&wk[j * HH + l]);
        sD[k][l] = acc;
    }
    __syncthreads();
    if (tid < HH) {
        float D0 = sD[0][tid], D1 = sD[1][tid], D2 = sD[2][tid];
        float v0 = 0.25f * (D0 + 2.f*D1 + D2);
        float v1 = 0.25f * (D0 - D2);
        float v2 = 0.25f * (D0 - 2.f*D1 + D2);
        float v3 = v1;
        v0 = fmaxf(v0, 0.f);  v1 = fmaxf(v1, 0.f);
        v2 = fmaxf(v2, 0.f);  v3 = fmaxf(v3, 0.f);
        float4 tv; tv.x = v0; tv.y = v1; tv.z = v2; tv.w = v3;
        *(float4*)&g_tX[((size_t)i * HH + tid) * RR] = tv;
        if (write_next) {
            int dst = src ^ 1;
            float p0 = v0 + v1 + v2 + v3;
            float p1 = v0 - v2;
            float p2 = v0 - v1 + v2 - v3;
            g_X02h[dst][(size_t)i * HH + tid] = __floats2half2_rn(p0, p2);
            ((__half*)g_X1h[dst])[(size_t)i * HH + tid] = __float2half_rn(p1);
        }
    }
}

// Head: 4 targets per block (grid 128), lin1_w cached in smem.
__global__ void k_head(const int* __restrict__ target_x, const int* __restrict__ target,
                       const float* __restrict__ l1w, const float* __restrict__ l1b,
                       const float* __restrict__ l2w, const float* __restrict__ l2b,
                       float* __restrict__ y_out) {
    extern __shared__ float dsm[];
    float* sw1 = dsm;                // 256*64 = 64KB
    float* sf  = sw1 + 256 * HH;     // 256
    float* sp  = sf + 256;           // 4*64
    float* szz = sp + 256;           // 64
    float* sy  = szz + 64;           // 16
    int tid = threadIdx.x;
    {
        const float4* w4 = (const float4*)l1w;
        float4* s4 = (float4*)sw1;
        for (int q = tid; q < 256 * HH / 4; q += 256) s4[q] = w4[q];
    }
    int h = tid & 63, part = tid >> 6;
    for (int tt = 0; tt < 4; tt++) {
        int t = blockIdx.x * 4 + tt;
        __syncthreads();
        int n = target_x[t];
        sf[tid] = g_tX[(size_t)n * 256 + tid];
        __syncthreads();
        float acc = 0.f;
        #pragma unroll 8
        for (int q = part * 64; q < part * 64 + 64; q++)
            acc += sf[q] * sw1[q * 64 + h];
        sp[part * 64 + h] = acc;
        __syncthreads();
        if (tid < HH) {
            float z = sp[tid] + sp[64 + tid] + sp[128 + tid] + sp[192 + tid] + l1b[tid];
            szz[tid] = fmaxf(z, 0.f);
        }
        __syncthreads();
        if (tid < CC) {
            float yv = l2b[tid];
            #pragma unroll 8
            for (int hh = 0; hh < HH; hh++) yv += szz[hh] * l2w[hh * CC + tid];
            sy[tid] = yv;
            y_out[t * CC + tid] = yv;
        }
        __syncthreads();
        if (tid == 0) {
            float mx = sy[0];
            for (int c = 1; c < CC; c++) mx = fmaxf(mx, sy[c]);
            float se = 0.f;
            for (int c = 0; c < CC; c++) se += expf(sy[c] - mx);
            g_losses[t] = mx + logf(se) - sy[target[t]];
        }
    }
}

__global__ void k_loss_reduce(float* __restrict__ loss_ptr) {
    __shared__ float s[256];
    int tid = threadIdx.x;
    s[tid] = g_losses[tid] + g_losses[tid + 256];
    __syncthreads();
    for (int o = 128; o > 0; o >>= 1) {
        if (tid < o) s[tid] += s[tid + o];
        __syncthreads();
    }
    if (tid == 0) *loss_ptr = s[0] / (float)TT;
}

extern "C" void kernel_launch(void* const* d_in, const int* in_sizes, int n_in,
                              void* d_out, int out_size) {
    const float* A        = (const float*)d_in[0];
    const float* X        = (const float*)d_in[1];
    const int*   target_x = (const int*)  d_in[2];
    const int*   target   = (const int*)  d_in[3];
    const float* gw1      = (const float*)d_in[4];
    const float* gb1      = (const float*)d_in[5];
    const float* gw2      = (const float*)d_in[6];
    const float* gb2      = (const float*)d_in[7];
    const float* mw       = (const float*)d_in[8];
    const float* l1w      = (const float*)d_in[9];
    const float* l1b      = (const float*)d_in[10];
    const float* l2w      = (const float*)d_in[11];
    const float* l2b      = (const float*)d_in[12];

    float* outf = (float*)d_out;
    float* loss_ptr = nullptr;
    float* y_dst;
    if (out_size >= TT * CC + 1)  { loss_ptr = outf; y_dst = outf + 1; }
    else if (out_size >= TT * CC) { y_dst = outf; }
    else {
        loss_ptr = outf;
        void* p = nullptr; cudaGetSymbolAddress(&p, g_yscratch);
        y_dst = (float*)p;
    }

    const int XW1_SMEM  = (FINN * HH + 32 * FINN) * 4;              // 48 KB
    const int HEAD_SMEM = (256 * HH + 256 + 256 + 64 + 16) * 4;     // ~66 KB
    cudaFuncSetAttribute(k_xw1,  cudaFuncAttributeMaxDynamicSharedMemorySize, XW1_SMEM);
    cudaFuncSetAttribute(k_head, cudaFuncAttributeMaxDynamicSharedMemorySize, HEAD_SMEM);

    // 1) sparsity pattern + degrees (single DRAM pass over A)
    k_build<<<RR * NN / 8, 256>>>(A);
    // 2) dw fill (MRGCO) + What transform
    k_prep<<<2048 + 32, 256>>>(mw);
    // 3) X @ W1 pre-scaled -> g_Y
    k_xw1<<<dim3(NN / 32, RR), 256, XW1_SMEM>>>(X, gw1);
    // 4) fused: aggregate(g_Y)+relu+(@W2), pre-scaled -> g_Y2
    k_gcn2<<<dim3(NN / 8, RR), 256>>>(gb1, gw2);
    // 5) second aggregation (g_Y2) + fp16 plane packing into buffer 0
    k_spmm_xhat<<<NN / 2, 256>>>(gb2);
    // 6) MRGCO layers (fp16 plane gathers, ping-pong buffers)
    for (int l = 0; l < LLAY; l++)
        k_mrgco<<<NN, 320>>>(l, l + 1 < LLAY, l & 1);
    // 7) head + deterministic loss reduction
    k_head<<<TT / 4, 256, HEAD_SMEM>>>(target_x, target, l1w, l1b, l2w, l2b, y_dst);
    if (loss_ptr) k_loss_reduce<<<1, 256>>>(loss_ptr);
}